// round 10
// baseline (speedup 1.0000x reference)
#include <cuda_runtime.h>
#include <cstdint>

#define Bsz 512
#define Ssz 100
#define Hsz 768
#define BS (Bsz*Ssz)
#define LAMBf 0.8f
#define STR 20   // smem row stride in words; conflict-free for m16n8k8 frag reads

// ---------------- scratch (allocation-free: __device__ globals) ----------------
__device__ float g_drep[Bsz*Hsz];
__device__ float g_wsimT[Hsz*Hsz];
__device__ float g_wd[Bsz*Hsz];
__device__ float g_cont[BS];
__device__ float g_rel[BS];
__device__ float g_T1[(size_t)BS*Hsz];            // 157 MB
__device__ float g_q[(size_t)Bsz*Ssz*Ssz];        // 20.5 MB

// ---------------- helpers ----------------
__device__ __forceinline__ void cpa16(uint32_t dst, const void* src) {
    asm volatile("cp.async.cg.shared.global [%0], [%1], 16;" :: "r"(dst), "l"(src));
}
__device__ __forceinline__ void cp_commit() { asm volatile("cp.async.commit_group;"); }
template<int N> __device__ __forceinline__ void cp_wait() {
    asm volatile("cp.async.wait_group %0;" :: "n"(N));
}
// tf32 mma: raw fp32 bits are valid tf32 operands (low mantissa bits ignored by HW)
__device__ __forceinline__ void mma_tf32(float c[4], unsigned a0, unsigned a1,
                                         unsigned a2, unsigned a3,
                                         unsigned b0, unsigned b1) {
    asm("mma.sync.aligned.m16n8k8.row.col.f32.tf32.tf32.f32 "
        "{%0,%1,%2,%3},{%4,%5,%6,%7},{%8,%9},{%0,%1,%2,%3};"
        : "+f"(c[0]), "+f"(c[1]), "+f"(c[2]), "+f"(c[3])
        : "r"(a0), "r"(a1), "r"(a2), "r"(a3), "r"(b0), "r"(b1));
}

// ---------------- d_rep = mean over S ----------------
__global__ void k_mean(const float* __restrict__ X) {
    int b = blockIdx.x;
    const float* Xb = X + (size_t)b*Ssz*Hsz;
    for (int h = threadIdx.x; h < Hsz; h += blockDim.x) {
        float s = 0.f;
        #pragma unroll 4
        for (int i = 0; i < Ssz; i++) s += Xb[(size_t)i*Hsz + h];
        g_drep[b*Hsz + h] = s * (1.f/Ssz);
    }
}

// ---------------- transpose (768x768) ----------------
__global__ void k_transpose(const float* __restrict__ W, float* __restrict__ Wt) {
    __shared__ float tile[32][33];
    int x = blockIdx.x*32 + threadIdx.x;
    int y = blockIdx.y*32 + threadIdx.y;
    #pragma unroll
    for (int dy = 0; dy < 32; dy += 8)
        tile[threadIdx.y+dy][threadIdx.x] = W[(size_t)(y+dy)*Hsz + x];
    __syncthreads();
    x = blockIdx.y*32 + threadIdx.x;
    y = blockIdx.x*32 + threadIdx.y;
    #pragma unroll
    for (int dy = 0; dy < 32; dy += 8)
        Wt[(size_t)(y+dy)*Hsz + x] = tile[threadIdx.x][threadIdx.y+dy];
}

// ---------------- warp-tile compute: 64x32 warp tile over 16-k slab ----------------
__device__ __forceinline__ void mma_slab_128(const unsigned* As, const unsigned* Bs,
                                             int m_off, int n_off, int grp, int qid,
                                             float acc[4][4][4]) {
    #pragma unroll
    for (int ka = 0; ka < 2; ka++) {
        int kb = ka*8;
        unsigned af[4][4], bf[4][2];
        #pragma unroll
        for (int mt = 0; mt < 4; mt++) {
            const unsigned* p = As + (m_off + mt*16 + grp)*STR + kb + qid;
            af[mt][0] = p[0]; af[mt][1] = p[8*STR]; af[mt][2] = p[4]; af[mt][3] = p[8*STR+4];
        }
        #pragma unroll
        for (int nt = 0; nt < 4; nt++) {
            const unsigned* p = Bs + (n_off + nt*8 + grp)*STR + kb + qid;
            bf[nt][0] = p[0]; bf[nt][1] = p[4];
        }
        #pragma unroll
        for (int mt = 0; mt < 4; mt++)
            #pragma unroll
            for (int nt = 0; nt < 4; nt++)
                mma_tf32(acc[mt][nt], af[mt][0],af[mt][1],af[mt][2],af[mt][3],
                         bf[nt][0], bf[nt][1]);
    }
}

// ---------------- tf32 NT GEMM, 2-stage cp.async, ONE sync per k-slab ---------------
// BM=BN=128, BK=16, 256 threads (8 warps 2x4, warp tile 64x32). M%128==N%128==K%16==0.
// Loop order wait(t) -> sync -> issue(t+1) -> mma(t): issue writes buffer (t-1)%2,
// whose readers (mma(t-1)) all passed this sync -> single barrier is race-free.
__global__ __launch_bounds__(256,2) void k_gemm_nt(const float* __restrict__ A,
                                                   const float* __restrict__ B,
                                                   float* __restrict__ C,
                                                   int M, int N, int K) {
    __shared__ float As[2][128*STR];
    __shared__ float Bs[2][128*STR];

    int tid  = threadIdx.x;
    int warp = tid >> 5, lane = tid & 31;
    int grp  = lane >> 2, qid = lane & 3;
    int m_off = (warp >> 2)*64, n_off = (warp & 3)*32;

    const float* Ab = A + (size_t)(blockIdx.y*128)*K;
    const float* Bb = B + (size_t)(blockIdx.x*128)*K;

    int r0 = tid >> 2;          // 0..63 (+64 second task)
    int c4 = (tid & 3)*4;

    uint32_t sA0 = (uint32_t)__cvta_generic_to_shared(&As[0][0]) + (r0*STR + c4)*4;
    uint32_t sB0 = (uint32_t)__cvta_generic_to_shared(&Bs[0][0]) + (r0*STR + c4)*4;
    const uint32_t stage = 128*STR*4;
    const uint32_t rowsk = 64*STR*4;

    float acc[4][4][4] = {};
    int ntiles = K/16;

    #define GISSUE(t) { uint32_t ds = ((t)&1)*stage; int kt = (t)*16; \
        cpa16(sA0+ds,       Ab + (size_t)r0*K      + kt + c4); \
        cpa16(sA0+ds+rowsk, Ab + (size_t)(r0+64)*K + kt + c4); \
        cpa16(sB0+ds,       Bb + (size_t)r0*K      + kt + c4); \
        cpa16(sB0+ds+rowsk, Bb + (size_t)(r0+64)*K + kt + c4); }

    GISSUE(0); cp_commit();

    for (int t = 0; t < ntiles; t++) {
        cp_wait<0>();
        __syncthreads();
        if (t+1 < ntiles) { GISSUE(t+1); cp_commit(); }
        int s = t & 1;
        mma_slab_128((const unsigned*)As[s], (const unsigned*)Bs[s],
                     m_off, n_off, grp, qid, acc);
    }
    #undef GISSUE

    float* Cb = C + (size_t)(blockIdx.y*128)*N + blockIdx.x*128;
    #pragma unroll
    for (int mt = 0; mt < 4; mt++) {
        int r = m_off + mt*16 + grp;
        #pragma unroll
        for (int nt = 0; nt < 4; nt++) {
            int c = n_off + nt*8 + qid*2;
            *(float2*)(Cb + (size_t)r*N + c)     = make_float2(acc[mt][nt][0], acc[mt][nt][1]);
            *(float2*)(Cb + (size_t)(r+8)*N + c) = make_float2(acc[mt][nt][2], acc[mt][nt][3]);
        }
    }
}

// ---------------- BM=32 variant for the thin wd GEMM (2-stage, static smem) --------
__global__ __launch_bounds__(256,2) void k_gemm_nt32(const float* __restrict__ A,
                                                     const float* __restrict__ B,
                                                     float* __restrict__ C,
                                                     int M, int N, int K) {
    __shared__ float As[2][32*STR];
    __shared__ float Bs[2][128*STR];
    int tid  = threadIdx.x;
    int warp = tid >> 5, lane = tid & 31;
    int grp  = lane >> 2, qid = lane & 3;
    int n_off = warp*16;

    const float* Ab = A + (size_t)(blockIdx.y*32)*K;
    const float* Bb = B + (size_t)(blockIdx.x*128)*K;

    int r0 = tid >> 2;
    int c4 = (tid & 3)*4;

    uint32_t sA0 = (uint32_t)__cvta_generic_to_shared(&As[0][0]) + (r0*STR + c4)*4;
    uint32_t sB0 = (uint32_t)__cvta_generic_to_shared(&Bs[0][0]) + (r0*STR + c4)*4;
    const uint32_t stageA = 32*STR*4, stageB = 128*STR*4;
    const uint32_t rowsk = 64*STR*4;
    bool doA = (tid < 128);

    float acc[2][2][4] = {};
    int ntiles = K/16;

    #define WISSUE(t) { uint32_t dA = ((t)&1)*stageA; uint32_t dB = ((t)&1)*stageB; int kt = (t)*16; \
        if (doA) cpa16(sA0 + dA, Ab + (size_t)r0*K + kt + c4); \
        cpa16(sB0 + dB,         Bb + (size_t)r0*K      + kt + c4); \
        cpa16(sB0 + dB + rowsk, Bb + (size_t)(r0+64)*K + kt + c4); }

    WISSUE(0); cp_commit();

    for (int t = 0; t < ntiles; t++) {
        cp_wait<0>();
        __syncthreads();
        if (t+1 < ntiles) { WISSUE(t+1); cp_commit(); }
        int s = t & 1;
        const unsigned* Au = (const unsigned*)As[s];
        const unsigned* Bu = (const unsigned*)Bs[s];
        #pragma unroll
        for (int ka = 0; ka < 2; ka++) {
            int kb = ka*8;
            unsigned af[2][4], bf[2][2];
            #pragma unroll
            for (int mt = 0; mt < 2; mt++) {
                const unsigned* p = Au + (mt*16 + grp)*STR + kb + qid;
                af[mt][0] = p[0]; af[mt][1] = p[8*STR]; af[mt][2] = p[4]; af[mt][3] = p[8*STR+4];
            }
            #pragma unroll
            for (int nt = 0; nt < 2; nt++) {
                const unsigned* p = Bu + (n_off + nt*8 + grp)*STR + kb + qid;
                bf[nt][0] = p[0]; bf[nt][1] = p[4];
            }
            #pragma unroll
            for (int mt = 0; mt < 2; mt++)
                #pragma unroll
                for (int nt = 0; nt < 2; nt++)
                    mma_tf32(acc[mt][nt], af[mt][0],af[mt][1],af[mt][2],af[mt][3],
                             bf[nt][0], bf[nt][1]);
        }
    }
    #undef WISSUE

    float* Cb = C + (size_t)(blockIdx.y*32)*N + blockIdx.x*128;
    #pragma unroll
    for (int mt = 0; mt < 2; mt++) {
        int r = mt*16 + grp;
        #pragma unroll
        for (int nt = 0; nt < 2; nt++) {
            int c = n_off + nt*8 + qid*2;
            *(float2*)(Cb + (size_t)r*N + c)     = make_float2(acc[mt][nt][0], acc[mt][nt][1]);
            *(float2*)(Cb + (size_t)(r+8)*N + c) = make_float2(acc[mt][nt][2], acc[mt][nt][3]);
        }
    }
}

// ---------------- cont & rel: one warp per (b,i) row ----------------
__global__ void k_cont_rel(const float* __restrict__ X, const float* __restrict__ Wc) {
    int row = blockIdx.x*8 + (threadIdx.x >> 5);
    if (row >= BS) return;
    int lane = threadIdx.x & 31;
    int b = row / Ssz;
    const float4* x  = (const float4*)(X + (size_t)row*Hsz);
    const float4* wc = (const float4*)Wc;
    const float4* wd = (const float4*)(g_wd + b*Hsz);
    float sc = 0.f, sr = 0.f;
    #pragma unroll
    for (int c = 0; c < Hsz/128; c++) {
        int k = c*32 + lane;
        float4 xv = x[k], a = wc[k], d = wd[k];
        sc += xv.x*a.x + xv.y*a.y + xv.z*a.z + xv.w*a.w;
        sr += xv.x*d.x + xv.y*d.y + xv.z*d.z + xv.w*d.w;
    }
    #pragma unroll
    for (int o = 16; o; o >>= 1) {
        sc += __shfl_down_sync(0xffffffffu, sc, o);
        sr += __shfl_down_sync(0xffffffffu, sr, o);
    }
    if (!lane) { g_cont[row] = sc; g_rel[row] = sr; }
}

// ---------------- per-batch sim = T1_b @ X_b^T (2-stage, 1 sync), fused q ----------
__global__ __launch_bounds__(256,2) void k_sim_q_mma(const float* __restrict__ X,
                                                     const int* __restrict__ mask,
                                                     const float* __restrict__ bptr) {
    __shared__ float As[2][128*STR];
    __shared__ float Bs[2][128*STR];
    __shared__ float cont_s[Ssz], rel_s[Ssz], mask_s[Ssz];

    int b = blockIdx.x;
    const float* T1b = g_T1 + (size_t)b*Ssz*Hsz;
    const float* Xb  = X    + (size_t)b*Ssz*Hsz;

    int tid  = threadIdx.x;
    int warp = tid >> 5, lane = tid & 31;
    int grp  = lane >> 2, qid = lane & 3;
    int m_off = (warp >> 2)*64, n_off = (warp & 3)*32;

    if (tid < Ssz) {
        cont_s[tid] = g_cont[b*Ssz + tid];
        rel_s[tid]  = g_rel[b*Ssz + tid];
        mask_s[tid] = (float)mask[b*Ssz + tid];
    }

    int r0 = tid >> 2;
    int c4 = (tid & 3)*4;
    int gr0 = (r0      < Ssz) ? r0      : Ssz-1;   // clamp dummies
    int gr1 = (r0 + 64 < Ssz) ? r0 + 64 : Ssz-1;

    uint32_t sA0 = (uint32_t)__cvta_generic_to_shared(&As[0][0]) + (r0*STR + c4)*4;
    uint32_t sB0 = (uint32_t)__cvta_generic_to_shared(&Bs[0][0]) + (r0*STR + c4)*4;
    const uint32_t stage = 128*STR*4;
    const uint32_t rowsk = 64*STR*4;

    float acc[4][4][4] = {};
    int ntiles = Hsz/16;

    #define SISSUE(t) { uint32_t ds = ((t)&1)*stage; int kt = (t)*16; \
        cpa16(sA0+ds,       T1b + (size_t)gr0*Hsz + kt + c4); \
        cpa16(sA0+ds+rowsk, T1b + (size_t)gr1*Hsz + kt + c4); \
        cpa16(sB0+ds,       Xb  + (size_t)gr0*Hsz + kt + c4); \
        cpa16(sB0+ds+rowsk, Xb  + (size_t)gr1*Hsz + kt + c4); }

    SISSUE(0); cp_commit();

    for (int t = 0; t < ntiles; t++) {
        cp_wait<0>();
        __syncthreads();
        if (t+1 < ntiles) { SISSUE(t+1); cp_commit(); }
        int s = t & 1;
        mma_slab_128((const unsigned*)As[s], (const unsigned*)Bs[s],
                     m_off, n_off, grp, qid, acc);
    }
    #undef SISSUE

    float bias = bptr[0];
    float* qb = g_q + (size_t)b*Ssz*Ssz;
    #pragma unroll
    for (int mt = 0; mt < 4; mt++) {
        int i0 = m_off + mt*16 + grp;
        #pragma unroll
        for (int nt = 0; nt < 4; nt++) {
            int j = n_off + nt*8 + qid*2;
            if (j >= Ssz) continue;
            float mj0 = mask_s[j], mj1 = mask_s[j+1];
            #pragma unroll
            for (int h = 0; h < 2; h++) {
                int i = i0 + h*8;
                if (i >= Ssz) continue;
                float mi = mask_s[i], ri = rel_s[i], ci = cont_s[i];
                float mm0 = mi*mj0, mm1 = mi*mj1;
                float a0 = (ri + acc[mt][nt][h*2+0])*mm0 + ci + bias;
                float a1 = (ri + acc[mt][nt][h*2+1])*mm1 + ci + bias;
                float q0 = mm0 / (1.f + __expf(-a0));
                float q1 = mm1 / (1.f + __expf(-a1));
                *(float2*)(qb + (size_t)i*Ssz + j) = make_float2(q0, q1);
            }
        }
    }
}

// ---------------- per-batch solve via Neumann series (split-dot, 256 thr) ---------
// qD column-stochastic => ||0.8 qD||_1 = 0.8; 48 iters -> err ~2e-5 << 1e-3.
__global__ void k_solve(float* __restrict__ out) {
    int b = blockIdx.x;
    __shared__ float Q[100][101];
    __shared__ float xv[100], part[2][100], inv[100];
    int tid = threadIdx.x;
    const float* qb = g_q + (size_t)b*Ssz*Ssz;
    for (int idx = tid; idx < Ssz*Ssz; idx += blockDim.x)
        Q[idx/100][idx%100] = qb[idx];
    __syncthreads();
    if (tid < 100) {
        float s = 0.f;
        for (int i = 0; i < 100; i++) s += Q[i][tid];
        inv[tid] = LAMBf / s;
        xv[tid]  = 1.f/Ssz;
    }
    __syncthreads();
    for (int idx = tid; idx < Ssz*Ssz; idx += blockDim.x) {
        int i = idx/100, j = idx%100;
        Q[i][j] *= inv[j];
    }
    __syncthreads();
    int half = tid / 100, i = tid % 100;   // tid<200 active
    for (int it = 0; it < 48; it++) {
        if (tid < 200) {
            float s = 0.f;
            int j0 = half*50;
            #pragma unroll 5
            for (int j = j0; j < j0+50; j++) s += Q[i][j]*xv[j];
            part[half][i] = s;
        }
        __syncthreads();
        if (tid < 100) xv[tid] = part[0][tid] + part[1][tid] + 1.f/Ssz;
        __syncthreads();
    }
    if (tid < 100) out[(size_t)b*Ssz + tid] = (1.f - LAMBf)*xv[tid];
}

// ---------------- launch (single stream, static smem only) ----------------
extern "C" void kernel_launch(void* const* d_in, const int* in_sizes, int n_in,
                              void* d_out, int out_size) {
    const float* X    = (const float*)d_in[0];
    const int*   mask = (const int*)  d_in[1];
    const float* Wc   = (const float*)d_in[2];
    const float* Wsim = (const float*)d_in[3];
    const float* Wrel = (const float*)d_in[4];
    const float* bm   = (const float*)d_in[5];
    float* out = (float*)d_out;

    float *drep, *wsimT, *wd, *T1;
    cudaGetSymbolAddress((void**)&drep,  g_drep);
    cudaGetSymbolAddress((void**)&wsimT, g_wsimT);
    cudaGetSymbolAddress((void**)&wd,    g_wd);
    cudaGetSymbolAddress((void**)&T1,    g_T1);

    // W_sim^T so big GEMM is NT form
    k_transpose<<<dim3(Hsz/32, Hsz/32), dim3(32, 8)>>>(Wsim, wsimT);
    // T1 = X @ W_sim   [51200,768] x [768,768]
    k_gemm_nt<<<dim3(Hsz/128, BS/128), 256>>>(X, wsimT, T1, BS, Hsz, Hsz);
    // d_rep; wd = drep @ Wrel^T
    k_mean<<<Bsz, 256>>>(X);
    k_gemm_nt32<<<dim3(Hsz/128, Bsz/32), 256>>>(drep, Wrel, wd, Bsz, Hsz, Hsz);
    // cont & rel
    k_cont_rel<<<BS/8, 256>>>(X, Wc);
    // sim + sigmoid -> q
    k_sim_q_mma<<<Bsz, 256>>>(X, mask, bm);
    // batched solve
    k_solve<<<Bsz, 256>>>(out);
}

// round 11
// speedup vs baseline: 1.0524x; 1.0524x over previous
#include <cuda_runtime.h>
#include <cstdint>

#define Bsz 512
#define Ssz 100
#define Hsz 768
#define BS (Bsz*Ssz)
#define LAMBf 0.8f
#define STR 20   // smem row stride in words; conflict-free for m16n8k8 frag reads

// ---------------- scratch (allocation-free: __device__ globals) ----------------
__device__ float g_drep[Bsz*Hsz];
__device__ float g_wsimT[Hsz*Hsz];
__device__ float g_wd[Bsz*Hsz];
__device__ float g_cont[BS];
__device__ float g_rel[BS];
__device__ float g_T1[(size_t)BS*Hsz];            // 157 MB
__device__ float g_q[(size_t)Bsz*Ssz*Ssz];        // 20.5 MB

// ---------------- helpers ----------------
__device__ __forceinline__ void cpa16(uint32_t dst, const void* src) {
    asm volatile("cp.async.cg.shared.global [%0], [%1], 16;" :: "r"(dst), "l"(src));
}
__device__ __forceinline__ void cp_commit() { asm volatile("cp.async.commit_group;"); }
template<int N> __device__ __forceinline__ void cp_wait() {
    asm volatile("cp.async.wait_group %0;" :: "n"(N));
}
// tf32 mma: raw fp32 bits are valid tf32 operands (low mantissa bits ignored by HW)
__device__ __forceinline__ void mma_tf32(float c[4], unsigned a0, unsigned a1,
                                         unsigned a2, unsigned a3,
                                         unsigned b0, unsigned b1) {
    asm("mma.sync.aligned.m16n8k8.row.col.f32.tf32.tf32.f32 "
        "{%0,%1,%2,%3},{%4,%5,%6,%7},{%8,%9},{%0,%1,%2,%3};"
        : "+f"(c[0]), "+f"(c[1]), "+f"(c[2]), "+f"(c[3])
        : "r"(a0), "r"(a1), "r"(a2), "r"(a3), "r"(b0), "r"(b1));
}

// ---------------- d_rep = mean over S ----------------
__global__ void k_mean(const float* __restrict__ X) {
    int b = blockIdx.x;
    const float* Xb = X + (size_t)b*Ssz*Hsz;
    for (int h = threadIdx.x; h < Hsz; h += blockDim.x) {
        float s = 0.f;
        #pragma unroll 4
        for (int i = 0; i < Ssz; i++) s += Xb[(size_t)i*Hsz + h];
        g_drep[b*Hsz + h] = s * (1.f/Ssz);
    }
}

// ---------------- transpose (768x768) ----------------
__global__ void k_transpose(const float* __restrict__ W, float* __restrict__ Wt) {
    __shared__ float tile[32][33];
    int x = blockIdx.x*32 + threadIdx.x;
    int y = blockIdx.y*32 + threadIdx.y;
    #pragma unroll
    for (int dy = 0; dy < 32; dy += 8)
        tile[threadIdx.y+dy][threadIdx.x] = W[(size_t)(y+dy)*Hsz + x];
    __syncthreads();
    x = blockIdx.y*32 + threadIdx.x;
    y = blockIdx.x*32 + threadIdx.y;
    #pragma unroll
    for (int dy = 0; dy < 32; dy += 8)
        Wt[(size_t)(y+dy)*Hsz + x] = tile[threadIdx.x][threadIdx.y+dy];
}

// ---------------- warp-tile compute: 64x32 warp tile over 16-k slab ----------------
__device__ __forceinline__ void mma_slab_128(const unsigned* As, const unsigned* Bs,
                                             int m_off, int n_off, int grp, int qid,
                                             float acc[4][4][4]) {
    #pragma unroll
    for (int ka = 0; ka < 2; ka++) {
        int kb = ka*8;
        unsigned af[4][4], bf[4][2];
        #pragma unroll
        for (int mt = 0; mt < 4; mt++) {
            const unsigned* p = As + (m_off + mt*16 + grp)*STR + kb + qid;
            af[mt][0] = p[0]; af[mt][1] = p[8*STR]; af[mt][2] = p[4]; af[mt][3] = p[8*STR+4];
        }
        #pragma unroll
        for (int nt = 0; nt < 4; nt++) {
            const unsigned* p = Bs + (n_off + nt*8 + grp)*STR + kb + qid;
            bf[nt][0] = p[0]; bf[nt][1] = p[4];
        }
        #pragma unroll
        for (int mt = 0; mt < 4; mt++)
            #pragma unroll
            for (int nt = 0; nt < 4; nt++)
                mma_tf32(acc[mt][nt], af[mt][0],af[mt][1],af[mt][2],af[mt][3],
                         bf[nt][0], bf[nt][1]);
    }
}

// ---------------- tf32 NT GEMM, cp.async 2-stage (round-6 form, best measured) -----
// BM=BN=128, BK=16, 256 threads (8 warps 2x4, warp tile 64x32). M%128==N%128==K%16==0.
__global__ __launch_bounds__(256,2) void k_gemm_nt(const float* __restrict__ A,
                                                   const float* __restrict__ B,
                                                   float* __restrict__ C,
                                                   int M, int N, int K) {
    __shared__ float As[2][128*STR];
    __shared__ float Bs[2][128*STR];
    int tid  = threadIdx.x;
    int warp = tid >> 5, lane = tid & 31;
    int grp  = lane >> 2, qid = lane & 3;
    int m_off = (warp >> 2)*64, n_off = (warp & 3)*32;

    const float* Ab = A + (size_t)(blockIdx.y*128)*K;
    const float* Bb = B + (size_t)(blockIdx.x*128)*K;

    int r0 = tid >> 2;          // 0..63 (+64 second task)
    int c4 = (tid & 3)*4;

    uint32_t sA0 = (uint32_t)__cvta_generic_to_shared(&As[0][0]) + (r0*STR + c4)*4;
    uint32_t sB0 = (uint32_t)__cvta_generic_to_shared(&Bs[0][0]) + (r0*STR + c4)*4;
    const uint32_t stage = 128*STR*4;
    const uint32_t rowsk = 64*STR*4;

    float acc[4][4][4] = {};
    int ntiles = K/16;

    #define GISSUE(t) { uint32_t ds = ((t)&1)*stage; int kt = (t)*16; \
        cpa16(sA0+ds,       Ab + (size_t)r0*K      + kt + c4); \
        cpa16(sA0+ds+rowsk, Ab + (size_t)(r0+64)*K + kt + c4); \
        cpa16(sB0+ds,       Bb + (size_t)r0*K      + kt + c4); \
        cpa16(sB0+ds+rowsk, Bb + (size_t)(r0+64)*K + kt + c4); }

    GISSUE(0); cp_commit();

    for (int t = 0; t < ntiles; t++) {
        if (t+1 < ntiles) { GISSUE(t+1); cp_commit(); cp_wait<1>(); }
        else              { cp_wait<0>(); }
        __syncthreads();
        int s = t & 1;
        mma_slab_128((const unsigned*)As[s], (const unsigned*)Bs[s],
                     m_off, n_off, grp, qid, acc);
        __syncthreads();
    }
    #undef GISSUE

    float* Cb = C + (size_t)(blockIdx.y*128)*N + blockIdx.x*128;
    #pragma unroll
    for (int mt = 0; mt < 4; mt++) {
        int r = m_off + mt*16 + grp;
        #pragma unroll
        for (int nt = 0; nt < 4; nt++) {
            int c = n_off + nt*8 + qid*2;
            *(float2*)(Cb + (size_t)r*N + c)     = make_float2(acc[mt][nt][0], acc[mt][nt][1]);
            *(float2*)(Cb + (size_t)(r+8)*N + c) = make_float2(acc[mt][nt][2], acc[mt][nt][3]);
        }
    }
}

// ---------------- BM=32 variant for the thin wd GEMM ----------------
__global__ __launch_bounds__(256,2) void k_gemm_nt32(const float* __restrict__ A,
                                                     const float* __restrict__ B,
                                                     float* __restrict__ C,
                                                     int M, int N, int K) {
    __shared__ float As[2][32*STR];
    __shared__ float Bs[2][128*STR];
    int tid  = threadIdx.x;
    int warp = tid >> 5, lane = tid & 31;
    int grp  = lane >> 2, qid = lane & 3;
    int n_off = warp*16;

    const float* Ab = A + (size_t)(blockIdx.y*32)*K;
    const float* Bb = B + (size_t)(blockIdx.x*128)*K;

    int r0 = tid >> 2;
    int c4 = (tid & 3)*4;

    uint32_t sA0 = (uint32_t)__cvta_generic_to_shared(&As[0][0]) + (r0*STR + c4)*4;
    uint32_t sB0 = (uint32_t)__cvta_generic_to_shared(&Bs[0][0]) + (r0*STR + c4)*4;
    const uint32_t stageA = 32*STR*4, stageB = 128*STR*4;
    const uint32_t rowsk = 64*STR*4;
    bool doA = (tid < 128);

    float acc[2][2][4] = {};
    int ntiles = K/16;

    if (doA) cpa16(sA0, Ab + (size_t)r0*K + c4);
    cpa16(sB0,         Bb + (size_t)r0*K      + c4);
    cpa16(sB0 + rowsk, Bb + (size_t)(r0+64)*K + c4);
    cp_commit();

    for (int t = 0; t < ntiles; t++) {
        int s = t & 1;
        if (t+1 < ntiles) {
            int kt = (t+1)*16;
            uint32_t dA = (t+1)&1 ? stageA : 0;
            uint32_t dB = (t+1)&1 ? stageB : 0;
            if (doA) cpa16(sA0 + dA, Ab + (size_t)r0*K + kt + c4);
            cpa16(sB0 + dB,         Bb + (size_t)r0*K      + kt + c4);
            cpa16(sB0 + dB + rowsk, Bb + (size_t)(r0+64)*K + kt + c4);
            cp_commit();
            cp_wait<1>();
        } else {
            cp_wait<0>();
        }
        __syncthreads();
        const unsigned* Au = (const unsigned*)As[s];
        const unsigned* Bu = (const unsigned*)Bs[s];
        #pragma unroll
        for (int ka = 0; ka < 2; ka++) {
            int kb = ka*8;
            unsigned af[2][4], bf[2][2];
            #pragma unroll
            for (int mt = 0; mt < 2; mt++) {
                const unsigned* p = Au + (mt*16 + grp)*STR + kb + qid;
                af[mt][0] = p[0]; af[mt][1] = p[8*STR]; af[mt][2] = p[4]; af[mt][3] = p[8*STR+4];
            }
            #pragma unroll
            for (int nt = 0; nt < 2; nt++) {
                const unsigned* p = Bu + (n_off + nt*8 + grp)*STR + kb + qid;
                bf[nt][0] = p[0]; bf[nt][1] = p[4];
            }
            #pragma unroll
            for (int mt = 0; mt < 2; mt++)
                #pragma unroll
                for (int nt = 0; nt < 2; nt++)
                    mma_tf32(acc[mt][nt], af[mt][0],af[mt][1],af[mt][2],af[mt][3],
                             bf[nt][0], bf[nt][1]);
        }
        __syncthreads();
    }

    float* Cb = C + (size_t)(blockIdx.y*32)*N + blockIdx.x*128;
    #pragma unroll
    for (int mt = 0; mt < 2; mt++) {
        int r = mt*16 + grp;
        #pragma unroll
        for (int nt = 0; nt < 2; nt++) {
            int c = n_off + nt*8 + qid*2;
            *(float2*)(Cb + (size_t)r*N + c)     = make_float2(acc[mt][nt][0], acc[mt][nt][1]);
            *(float2*)(Cb + (size_t)(r+8)*N + c) = make_float2(acc[mt][nt][2], acc[mt][nt][3]);
        }
    }
}

// ---------------- cont & rel: one warp per (b,i) row ----------------
__global__ void k_cont_rel(const float* __restrict__ X, const float* __restrict__ Wc) {
    int row = blockIdx.x*8 + (threadIdx.x >> 5);
    if (row >= BS) return;
    int lane = threadIdx.x & 31;
    int b = row / Ssz;
    const float4* x  = (const float4*)(X + (size_t)row*Hsz);
    const float4* wc = (const float4*)Wc;
    const float4* wd = (const float4*)(g_wd + b*Hsz);
    float sc = 0.f, sr = 0.f;
    #pragma unroll
    for (int c = 0; c < Hsz/128; c++) {
        int k = c*32 + lane;
        float4 xv = x[k], a = wc[k], d = wd[k];
        sc += xv.x*a.x + xv.y*a.y + xv.z*a.z + xv.w*a.w;
        sr += xv.x*d.x + xv.y*d.y + xv.z*d.z + xv.w*d.w;
    }
    #pragma unroll
    for (int o = 16; o; o >>= 1) {
        sc += __shfl_down_sync(0xffffffffu, sc, o);
        sr += __shfl_down_sync(0xffffffffu, sr, o);
    }
    if (!lane) { g_cont[row] = sc; g_rel[row] = sr; }
}

// ---------------- per-batch sim = T1_b @ X_b^T (2-stage cp.async), fused q ---------
__global__ __launch_bounds__(256,2) void k_sim_q_mma(const float* __restrict__ X,
                                                     const int* __restrict__ mask,
                                                     const float* __restrict__ bptr) {
    __shared__ float As[2][128*STR];
    __shared__ float Bs[2][128*STR];
    __shared__ float cont_s[Ssz], rel_s[Ssz], mask_s[Ssz];

    int b = blockIdx.x;
    const float* T1b = g_T1 + (size_t)b*Ssz*Hsz;
    const float* Xb  = X    + (size_t)b*Ssz*Hsz;

    int tid  = threadIdx.x;
    int warp = tid >> 5, lane = tid & 31;
    int grp  = lane >> 2, qid = lane & 3;
    int m_off = (warp >> 2)*64, n_off = (warp & 3)*32;

    if (tid < Ssz) {
        cont_s[tid] = g_cont[b*Ssz + tid];
        rel_s[tid]  = g_rel[b*Ssz + tid];
        mask_s[tid] = (float)mask[b*Ssz + tid];
    }

    int r0 = tid >> 2;
    int c4 = (tid & 3)*4;
    int gr0 = (r0      < Ssz) ? r0      : Ssz-1;   // clamp dummies
    int gr1 = (r0 + 64 < Ssz) ? r0 + 64 : Ssz-1;

    uint32_t sA0 = (uint32_t)__cvta_generic_to_shared(&As[0][0]) + (r0*STR + c4)*4;
    uint32_t sB0 = (uint32_t)__cvta_generic_to_shared(&Bs[0][0]) + (r0*STR + c4)*4;
    const uint32_t stage = 128*STR*4;
    const uint32_t rowsk = 64*STR*4;

    float acc[4][4][4] = {};
    int ntiles = Hsz/16;

    #define SISSUE(t) { uint32_t ds = ((t)&1)*stage; int kt = (t)*16; \
        cpa16(sA0+ds,       T1b + (size_t)gr0*Hsz + kt + c4); \
        cpa16(sA0+ds+rowsk, T1b + (size_t)gr1*Hsz + kt + c4); \
        cpa16(sB0+ds,       Xb  + (size_t)gr0*Hsz + kt + c4); \
        cpa16(sB0+ds+rowsk, Xb  + (size_t)gr1*Hsz + kt + c4); }

    SISSUE(0); cp_commit();

    for (int t = 0; t < ntiles; t++) {
        if (t+1 < ntiles) { SISSUE(t+1); cp_commit(); cp_wait<1>(); }
        else              { cp_wait<0>(); }
        __syncthreads();
        int s = t & 1;
        mma_slab_128((const unsigned*)As[s], (const unsigned*)Bs[s],
                     m_off, n_off, grp, qid, acc);
        __syncthreads();
    }
    #undef SISSUE

    float bias = bptr[0];
    float* qb = g_q + (size_t)b*Ssz*Ssz;
    #pragma unroll
    for (int mt = 0; mt < 4; mt++) {
        int i0 = m_off + mt*16 + grp;
        #pragma unroll
        for (int nt = 0; nt < 4; nt++) {
            int j = n_off + nt*8 + qid*2;
            if (j >= Ssz) continue;
            float mj0 = mask_s[j], mj1 = mask_s[j+1];
            #pragma unroll
            for (int h = 0; h < 2; h++) {
                int i = i0 + h*8;
                if (i >= Ssz) continue;
                float mi = mask_s[i], ri = rel_s[i], ci = cont_s[i];
                float mm0 = mi*mj0, mm1 = mi*mj1;
                float a0 = (ri + acc[mt][nt][h*2+0])*mm0 + ci + bias;
                float a1 = (ri + acc[mt][nt][h*2+1])*mm1 + ci + bias;
                float q0 = mm0 / (1.f + __expf(-a0));
                float q1 = mm1 / (1.f + __expf(-a1));
                *(float2*)(qb + (size_t)i*Ssz + j) = make_float2(q0, q1);
            }
        }
    }
}

// ---------------- per-batch solve via Neumann series (split-dot, 256 thr) ---------
// qD column-stochastic => ||0.8 qD||_1 = 0.8; 48 iters -> err ~2e-5 << 1e-3.
__global__ void k_solve(float* __restrict__ out) {
    int b = blockIdx.x;
    __shared__ float Q[100][101];
    __shared__ float xv[100], part[2][100], inv[100];
    int tid = threadIdx.x;
    const float* qb = g_q + (size_t)b*Ssz*Ssz;
    for (int idx = tid; idx < Ssz*Ssz; idx += blockDim.x)
        Q[idx/100][idx%100] = qb[idx];
    __syncthreads();
    if (tid < 100) {
        float s = 0.f;
        for (int i = 0; i < 100; i++) s += Q[i][tid];
        inv[tid] = LAMBf / s;
        xv[tid]  = 1.f/Ssz;
    }
    __syncthreads();
    for (int idx = tid; idx < Ssz*Ssz; idx += blockDim.x) {
        int i = idx/100, j = idx%100;
        Q[i][j] *= inv[j];
    }
    __syncthreads();
    int half = tid / 100, i = tid % 100;   // tid<200 active
    for (int it = 0; it < 48; it++) {
        if (tid < 200) {
            float s0 = 0.f, s1 = 0.f;        // 2-way ILP on the reduction chain
            int j0 = half*50;
            #pragma unroll 5
            for (int j = j0; j < j0+50; j += 2) { s0 += Q[i][j]*xv[j]; s1 += Q[i][j+1]*xv[j+1]; }
            part[half][i] = s0 + s1;
        }
        __syncthreads();
        if (tid < 100) xv[tid] = part[0][tid] + part[1][tid] + 1.f/Ssz;
        __syncthreads();
    }
    if (tid < 100) out[(size_t)b*Ssz + tid] = (1.f - LAMBf)*xv[tid];
}

// ---------------- launch: two-stream fork (capture-legal event fork/join) ----------
extern "C" void kernel_launch(void* const* d_in, const int* in_sizes, int n_in,
                              void* d_out, int out_size) {
    const float* X    = (const float*)d_in[0];
    const int*   mask = (const int*)  d_in[1];
    const float* Wc   = (const float*)d_in[2];
    const float* Wsim = (const float*)d_in[3];
    const float* Wrel = (const float*)d_in[4];
    const float* bm   = (const float*)d_in[5];
    float* out = (float*)d_out;

    float *drep, *wsimT, *wd, *T1;
    cudaGetSymbolAddress((void**)&drep,  g_drep);
    cudaGetSymbolAddress((void**)&wsimT, g_wsimT);
    cudaGetSymbolAddress((void**)&wd,    g_wd);
    cudaGetSymbolAddress((void**)&T1,    g_T1);

    // Fork: branch B (mean -> wd GEMM -> cont_rel) is independent of branch A
    // (transpose -> big GEMM); run it on a side stream, join before sim_q.
    cudaStream_t s2 = 0;
    cudaEvent_t  e1 = 0, e2 = 0;
    bool fork = (cudaStreamCreateWithFlags(&s2, cudaStreamNonBlocking) == cudaSuccess);
    if (fork) fork = (cudaEventCreateWithFlags(&e1, cudaEventDisableTiming) == cudaSuccess);
    if (fork) fork = (cudaEventCreateWithFlags(&e2, cudaEventDisableTiming) == cudaSuccess);
    if (fork) fork = (cudaEventRecord(e1, 0) == cudaSuccess) &&
                     (cudaStreamWaitEvent(s2, e1, 0) == cudaSuccess);
    cudaStream_t sb = fork ? s2 : (cudaStream_t)0;

    // Branch A (main stream)
    k_transpose<<<dim3(Hsz/32, Hsz/32), dim3(32, 8)>>>(Wsim, wsimT);
    k_gemm_nt<<<dim3(Hsz/128, BS/128), 256>>>(X, wsimT, T1, BS, Hsz, Hsz);

    // Branch B (side stream)
    k_mean<<<Bsz, 256, 0, sb>>>(X);
    k_gemm_nt32<<<dim3(Hsz/128, Bsz/32), 256, 0, sb>>>(drep, Wrel, wd, Bsz, Hsz, Hsz);
    k_cont_rel<<<BS/8, 256, 0, sb>>>(X, Wc);

    if (fork) {
        cudaEventRecord(e2, s2);
        cudaStreamWaitEvent(0, e2, 0);
    }

    // Join: sim + sigmoid -> q, then batched solve
    k_sim_q_mma<<<Bsz, 256>>>(X, mask, bm);
    k_solve<<<Bsz, 256>>>(out);

    // Destroy host-side objects only when NOT capturing (during capture they
    // are graph participants; leaking them on the single capture call is
    // host-side only and allocation-rule-compliant).
    cudaStreamCaptureStatus cs = cudaStreamCaptureStatusNone;
    cudaStreamIsCapturing(0, &cs);
    if (cs == cudaStreamCaptureStatusNone) {
        if (e1) cudaEventDestroy(e1);
        if (e2) cudaEventDestroy(e2);
        if (s2) cudaStreamDestroy(s2);
    }
}

// round 17
// speedup vs baseline: 1.4640x; 1.3912x over previous
#include <cuda_runtime.h>
#include <cuda_fp16.h>
#include <cstdint>

#define Bsz 512
#define Ssz 100
#define Hsz 768
#define BS (Bsz*Ssz)
#define LAMBf 0.8f
#define STR 20   // smem row stride in 32-bit words (16 used + 4 pad)

// ---------------- scratch (allocation-free: __device__ globals) ----------------
__device__ float  g_drep[Bsz*Hsz];
__device__ __half g_wsimTh[Hsz*Hsz];              // W_sim^T in fp16
__device__ __half g_Xh[(size_t)BS*Hsz];           // X in fp16 (78 MB)
__device__ float  g_wd[Bsz*Hsz];
__device__ float  g_cont[BS];
__device__ float  g_rel[BS];
__device__ __half g_T1h[(size_t)BS*Hsz];          // X @ W_sim in fp16 (78 MB)
__device__ float  g_q[(size_t)Bsz*Ssz*Ssz];       // 20.5 MB

// ---------------- helpers ----------------
__device__ __forceinline__ void cpa16(uint32_t dst, const void* src) {
    asm volatile("cp.async.cg.shared.global [%0], [%1], 16;" :: "r"(dst), "l"(src));
}
__device__ __forceinline__ void cp_commit() { asm volatile("cp.async.commit_group;"); }
template<int N> __device__ __forceinline__ void cp_wait() {
    asm volatile("cp.async.wait_group %0;" :: "n"(N));
}
__device__ __forceinline__ uint32_t smem_u32(const void* p) {
    return (uint32_t)__cvta_generic_to_shared(p);
}
// fp16 mma, fp32 accumulate: 4096 FLOP/instr (2x the tf32 m16n8k8 rate)
__device__ __forceinline__ void mma_f16(float c[4], unsigned a0, unsigned a1,
                                        unsigned a2, unsigned a3,
                                        unsigned b0, unsigned b1) {
    asm("mma.sync.aligned.m16n8k16.row.col.f32.f16.f16.f32 "
        "{%0,%1,%2,%3},{%4,%5,%6,%7},{%8,%9},{%0,%1,%2,%3};"
        : "+f"(c[0]), "+f"(c[1]), "+f"(c[2]), "+f"(c[3])
        : "r"(a0), "r"(a1), "r"(a2), "r"(a3), "r"(b0), "r"(b1));
}
// legacy tf32 mma (kept for the small wd GEMM)
__device__ __forceinline__ void mma_tf32(float c[4], unsigned a0, unsigned a1,
                                         unsigned a2, unsigned a3,
                                         unsigned b0, unsigned b1) {
    asm("mma.sync.aligned.m16n8k8.row.col.f32.tf32.tf32.f32 "
        "{%0,%1,%2,%3},{%4,%5,%6,%7},{%8,%9},{%0,%1,%2,%3};"
        : "+f"(c[0]), "+f"(c[1]), "+f"(c[2]), "+f"(c[3])
        : "r"(a0), "r"(a1), "r"(a2), "r"(a3), "r"(b0), "r"(b1));
}

// ---------------- X f32 -> fp16 ----------------
__global__ void k_convX(const float4* __restrict__ X4, __half2* __restrict__ out2, int n4) {
    for (int i = blockIdx.x*blockDim.x + threadIdx.x; i < n4; i += gridDim.x*blockDim.x) {
        float4 v = X4[i];
        out2[2*i]   = __floats2half2_rn(v.x, v.y);
        out2[2*i+1] = __floats2half2_rn(v.z, v.w);
    }
}

// ---------------- W_sim transpose + convert to fp16 ----------------
__global__ void k_transpose_h(const float* __restrict__ W, __half* __restrict__ Wt) {
    __shared__ float tile[32][33];
    int x = blockIdx.x*32 + threadIdx.x;
    int y = blockIdx.y*32 + threadIdx.y;
    #pragma unroll
    for (int dy = 0; dy < 32; dy += 8)
        tile[threadIdx.y+dy][threadIdx.x] = W[(size_t)(y+dy)*Hsz + x];
    __syncthreads();
    x = blockIdx.y*32 + threadIdx.x;
    y = blockIdx.x*32 + threadIdx.y;
    #pragma unroll
    for (int dy = 0; dy < 32; dy += 8)
        Wt[(size_t)(y+dy)*Hsz + x] = __float2half_rn(tile[threadIdx.x][threadIdx.y+dy]);
}

// ---------------- fp16 warp-tile compute: 64x32 warp tile over K=32 slab ----------
// smem word = half2; word layout per row: 16 words cover 32 halves of K.
// m16n8k16 fragments: a0=[grp][w qid], a1=[grp+8][qid], a2=[grp][qid+4], a3=[grp+8][qid+4]
// (identical word-index pattern to the tf32 path, verified vs PTX fragment spec).
__device__ __forceinline__ void mma_slab_h(const unsigned* As, const unsigned* Bs,
                                           int m_off, int n_off, int grp, int qid,
                                           float acc[4][4][4]) {
    #pragma unroll
    for (int ka = 0; ka < 2; ka++) {           // two k16 steps per 32-half slab
        int kb = ka*8;
        unsigned af[4][4], bf[4][2];
        #pragma unroll
        for (int mt = 0; mt < 4; mt++) {
            const unsigned* p = As + (m_off + mt*16 + grp)*STR + kb + qid;
            af[mt][0] = p[0]; af[mt][1] = p[8*STR]; af[mt][2] = p[4]; af[mt][3] = p[8*STR+4];
        }
        #pragma unroll
        for (int nt = 0; nt < 4; nt++) {
            const unsigned* p = Bs + (n_off + nt*8 + grp)*STR + kb + qid;
            bf[nt][0] = p[0]; bf[nt][1] = p[4];
        }
        #pragma unroll
        for (int mt = 0; mt < 4; mt++)
            #pragma unroll
            for (int nt = 0; nt < 4; nt++)
                mma_f16(acc[mt][nt], af[mt][0],af[mt][1],af[mt][2],af[mt][3],
                        bf[nt][0], bf[nt][1]);
    }
}

// ---------------- fp16 NT GEMM: C[M,N](half) = A[M,K] @ B[N,K]^T, all half --------
// BM=BN=128, K-slab=32 halves (64B/row), 2-stage cp.async (round-6 proven form).
__global__ __launch_bounds__(256,2) void k_gemm_h(const __half* __restrict__ A,
                                                  const __half* __restrict__ B,
                                                  __half* __restrict__ C,
                                                  int M, int N, int K) {
    __shared__ uint32_t As[2][128*STR];
    __shared__ uint32_t Bs[2][128*STR];
    int tid  = threadIdx.x;
    int warp = tid >> 5, lane = tid & 31;
    int grp  = lane >> 2, qid = lane & 3;
    int m_off = (warp >> 2)*64, n_off = (warp & 3)*32;

    const __half* Ab = A + (size_t)(blockIdx.y*128)*K;
    const __half* Bb = B + (size_t)(blockIdx.x*128)*K;

    int r0 = tid >> 2;          // 0..63 (+64 second task)
    int u  = tid & 3;           // 16B unit within 64B row

    uint32_t sA0 = smem_u32(&As[0][0]) + (r0*STR + u*4)*4;
    uint32_t sB0 = smem_u32(&Bs[0][0]) + (r0*STR + u*4)*4;
    const uint32_t stage = 128*STR*4;
    const uint32_t rowsk = 64*STR*4;

    float acc[4][4][4] = {};
    int ntiles = K/32;          // 24 for K=768

    #define GISSUE(t) { uint32_t ds = ((t)&1)*stage; int kt = (t)*32; \
        cpa16(sA0+ds,       Ab + (size_t)r0*K      + kt + u*8); \
        cpa16(sA0+ds+rowsk, Ab + (size_t)(r0+64)*K + kt + u*8); \
        cpa16(sB0+ds,       Bb + (size_t)r0*K      + kt + u*8); \
        cpa16(sB0+ds+rowsk, Bb + (size_t)(r0+64)*K + kt + u*8); }

    GISSUE(0); cp_commit();

    for (int t = 0; t < ntiles; t++) {
        if (t+1 < ntiles) { GISSUE(t+1); cp_commit(); cp_wait<1>(); }
        else              { cp_wait<0>(); }
        __syncthreads();
        int s = t & 1;
        mma_slab_h(As[s], Bs[s], m_off, n_off, grp, qid, acc);
        __syncthreads();
    }
    #undef GISSUE

    __half* Cb = C + (size_t)(blockIdx.y*128)*N + blockIdx.x*128;
    #pragma unroll
    for (int mt = 0; mt < 4; mt++) {
        int r = m_off + mt*16 + grp;
        #pragma unroll
        for (int nt = 0; nt < 4; nt++) {
            int c = n_off + nt*8 + qid*2;
            *(__half2*)(Cb + (size_t)r*N + c)     = __floats2half2_rn(acc[mt][nt][0], acc[mt][nt][1]);
            *(__half2*)(Cb + (size_t)(r+8)*N + c) = __floats2half2_rn(acc[mt][nt][2], acc[mt][nt][3]);
        }
    }
}

// ---------------- BM=32 tf32 variant for the thin wd GEMM (unchanged) -------------
__global__ __launch_bounds__(256,2) void k_gemm_nt32(const float* __restrict__ A,
                                                     const float* __restrict__ B,
                                                     float* __restrict__ C,
                                                     int M, int N, int K) {
    __shared__ float As[2][32*STR];
    __shared__ float Bs[2][128*STR];
    int tid  = threadIdx.x;
    int warp = tid >> 5, lane = tid & 31;
    int grp  = lane >> 2, qid = lane & 3;
    int n_off = warp*16;

    const float* Ab = A + (size_t)(blockIdx.y*32)*K;
    const float* Bb = B + (size_t)(blockIdx.x*128)*K;

    int r0 = tid >> 2;
    int c4 = (tid & 3)*4;

    uint32_t sA0 = smem_u32(&As[0][0]) + (r0*STR + c4)*4;
    uint32_t sB0 = smem_u32(&Bs[0][0]) + (r0*STR + c4)*4;
    const uint32_t stageA = 32*STR*4, stageB = 128*STR*4;
    const uint32_t rowsk = 64*STR*4;
    bool doA = (tid < 128);

    float acc[2][2][4] = {};
    int ntiles = K/16;

    if (doA) cpa16(sA0, Ab + (size_t)r0*K + c4);
    cpa16(sB0,         Bb + (size_t)r0*K      + c4);
    cpa16(sB0 + rowsk, Bb + (size_t)(r0+64)*K + c4);
    cp_commit();

    for (int t = 0; t < ntiles; t++) {
        int s = t & 1;
        if (t+1 < ntiles) {
            int kt = (t+1)*16;
            uint32_t dA = (t+1)&1 ? stageA : 0;
            uint32_t dB = (t+1)&1 ? stageB : 0;
            if (doA) cpa16(sA0 + dA, Ab + (size_t)r0*K + kt + c4);
            cpa16(sB0 + dB,         Bb + (size_t)r0*K      + kt + c4);
            cpa16(sB0 + dB + rowsk, Bb + (size_t)(r0+64)*K + kt + c4);
            cp_commit();
            cp_wait<1>();
        } else {
            cp_wait<0>();
        }
        __syncthreads();
        const unsigned* Au = (const unsigned*)As[s];
        const unsigned* Bu = (const unsigned*)Bs[s];
        #pragma unroll
        for (int ka = 0; ka < 2; ka++) {
            int kb = ka*8;
            unsigned af[2][4], bf[2][2];
            #pragma unroll
            for (int mt = 0; mt < 2; mt++) {
                const unsigned* p = Au + (mt*16 + grp)*STR + kb + qid;
                af[mt][0] = p[0]; af[mt][1] = p[8*STR]; af[mt][2] = p[4]; af[mt][3] = p[8*STR+4];
            }
            #pragma unroll
            for (int nt = 0; nt < 2; nt++) {
                const unsigned* p = Bu + (n_off + nt*8 + grp)*STR + kb + qid;
                bf[nt][0] = p[0]; bf[nt][1] = p[4];
            }
            #pragma unroll
            for (int mt = 0; mt < 2; mt++)
                #pragma unroll
                for (int nt = 0; nt < 2; nt++)
                    mma_tf32(acc[mt][nt], af[mt][0],af[mt][1],af[mt][2],af[mt][3],
                             bf[nt][0], bf[nt][1]);
        }
        __syncthreads();
    }

    float* Cb = C + (size_t)(blockIdx.y*32)*N + blockIdx.x*128;
    #pragma unroll
    for (int mt = 0; mt < 2; mt++) {
        int r = mt*16 + grp;
        #pragma unroll
        for (int nt = 0; nt < 2; nt++) {
            int c = n_off + nt*8 + qid*2;
            *(float2*)(Cb + (size_t)r*N + c)     = make_float2(acc[mt][nt][0], acc[mt][nt][1]);
            *(float2*)(Cb + (size_t)(r+8)*N + c) = make_float2(acc[mt][nt][2], acc[mt][nt][3]);
        }
    }
}

// ---------------- d_rep = mean over S ----------------
__global__ void k_mean(const float* __restrict__ X) {
    int b = blockIdx.x;
    const float* Xb = X + (size_t)b*Ssz*Hsz;
    for (int h = threadIdx.x; h < Hsz; h += blockDim.x) {
        float s = 0.f;
        #pragma unroll 4
        for (int i = 0; i < Ssz; i++) s += Xb[(size_t)i*Hsz + h];
        g_drep[b*Hsz + h] = s * (1.f/Ssz);
    }
}

// ---------------- cont & rel: one warp per (b,i) row ----------------
__global__ void k_cont_rel(const float* __restrict__ X, const float* __restrict__ Wc) {
    int row = blockIdx.x*8 + (threadIdx.x >> 5);
    if (row >= BS) return;
    int lane = threadIdx.x & 31;
    int b = row / Ssz;
    const float4* x  = (const float4*)(X + (size_t)row*Hsz);
    const float4* wc = (const float4*)Wc;
    const float4* wd = (const float4*)(g_wd + b*Hsz);
    float sc = 0.f, sr = 0.f;
    #pragma unroll
    for (int c = 0; c < Hsz/128; c++) {
        int k = c*32 + lane;
        float4 xv = x[k], a = wc[k], d = wd[k];
        sc += xv.x*a.x + xv.y*a.y + xv.z*a.z + xv.w*a.w;
        sr += xv.x*d.x + xv.y*d.y + xv.z*d.z + xv.w*d.w;
    }
    #pragma unroll
    for (int o = 16; o; o >>= 1) {
        sc += __shfl_down_sync(0xffffffffu, sc, o);
        sr += __shfl_down_sync(0xffffffffu, sr, o);
    }
    if (!lane) { g_cont[row] = sc; g_rel[row] = sr; }
}

// ---------------- per-batch sim = T1_b @ X_b^T (fp16 mma, cp.async), fused q -------
__global__ __launch_bounds__(256,2) void k_sim_q_h(const int* __restrict__ mask,
                                                   const float* __restrict__ bptr) {
    __shared__ uint32_t As[2][128*STR];
    __shared__ uint32_t Bs[2][128*STR];
    __shared__ float cont_s[Ssz], rel_s[Ssz], mask_s[Ssz];

    int b = blockIdx.x;
    const __half* T1b = g_T1h + (size_t)b*Ssz*Hsz;
    const __half* Xb  = g_Xh  + (size_t)b*Ssz*Hsz;

    int tid  = threadIdx.x;
    int warp = tid >> 5, lane = tid & 31;
    int grp  = lane >> 2, qid = lane & 3;
    int m_off = (warp >> 2)*64, n_off = (warp & 3)*32;

    if (tid < Ssz) {
        cont_s[tid] = g_cont[b*Ssz + tid];
        rel_s[tid]  = g_rel[b*Ssz + tid];
        mask_s[tid] = (float)mask[b*Ssz + tid];
    }

    int r0 = tid >> 2;
    int u  = tid & 3;
    int gr0 = (r0      < Ssz) ? r0      : Ssz-1;   // clamp dummies
    int gr1 = (r0 + 64 < Ssz) ? r0 + 64 : Ssz-1;

    uint32_t sA0 = smem_u32(&As[0][0]) + (r0*STR + u*4)*4;
    uint32_t sB0 = smem_u32(&Bs[0][0]) + (r0*STR + u*4)*4;
    const uint32_t stage = 128*STR*4;
    const uint32_t rowsk = 64*STR*4;

    float acc[4][4][4] = {};
    int ntiles = Hsz/32;       // 24

    #define SISSUE(t) { uint32_t ds = ((t)&1)*stage; int kt = (t)*32; \
        cpa16(sA0+ds,       T1b + (size_t)gr0*Hsz + kt + u*8); \
        cpa16(sA0+ds+rowsk, T1b + (size_t)gr1*Hsz + kt + u*8); \
        cpa16(sB0+ds,       Xb  + (size_t)gr0*Hsz + kt + u*8); \
        cpa16(sB0+ds+rowsk, Xb  + (size_t)gr1*Hsz + kt + u*8); }

    SISSUE(0); cp_commit();

    for (int t = 0; t < ntiles; t++) {
        if (t+1 < ntiles) { SISSUE(t+1); cp_commit(); cp_wait<1>(); }
        else              { cp_wait<0>(); }
        __syncthreads();
        int s = t & 1;
        mma_slab_h(As[s], Bs[s], m_off, n_off, grp, qid, acc);
        __syncthreads();
    }
    #undef SISSUE

    float bias = bptr[0];
    float* qb = g_q + (size_t)b*Ssz*Ssz;
    #pragma unroll
    for (int mt = 0; mt < 4; mt++) {
        int i0 = m_off + mt*16 + grp;
        #pragma unroll
        for (int nt = 0; nt < 4; nt++) {
            int j = n_off + nt*8 + qid*2;
            if (j >= Ssz) continue;
            float mj0 = mask_s[j], mj1 = mask_s[j+1];
            #pragma unroll
            for (int h = 0; h < 2; h++) {
                int i = i0 + h*8;
                if (i >= Ssz) continue;
                float mi = mask_s[i], ri = rel_s[i], ci = cont_s[i];
                float mm0 = mi*mj0, mm1 = mi*mj1;
                float a0 = (ri + acc[mt][nt][h*2+0])*mm0 + ci + bias;
                float a1 = (ri + acc[mt][nt][h*2+1])*mm1 + ci + bias;
                float q0 = mm0 / (1.f + __expf(-a0));
                float q1 = mm1 / (1.f + __expf(-a1));
                *(float2*)(qb + (size_t)i*Ssz + j) = make_float2(q0, q1);
            }
        }
    }
}

// ---------------- per-batch solve via Neumann series ----------------
__global__ void k_solve(float* __restrict__ out) {
    int b = blockIdx.x;
    __shared__ float Q[100][101];
    __shared__ float xv[100], part[2][100], inv[100];
    int tid = threadIdx.x;
    const float* qb = g_q + (size_t)b*Ssz*Ssz;
    for (int idx = tid; idx < Ssz*Ssz; idx += blockDim.x)
        Q[idx/100][idx%100] = qb[idx];
    __syncthreads();
    if (tid < 100) {
        float s = 0.f;
        for (int i = 0; i < 100; i++) s += Q[i][tid];
        inv[tid] = LAMBf / s;
        xv[tid]  = 1.f/Ssz;
    }
    __syncthreads();
    for (int idx = tid; idx < Ssz*Ssz; idx += blockDim.x) {
        int i = idx/100, j = idx%100;
        Q[i][j] *= inv[j];
    }
    __syncthreads();
    int half = tid / 100, i = tid % 100;
    for (int it = 0; it < 48; it++) {
        if (tid < 200) {
            float s0 = 0.f, s1 = 0.f;
            int j0 = half*50;
            #pragma unroll 5
            for (int j = j0; j < j0+50; j += 2) { s0 += Q[i][j]*xv[j]; s1 += Q[i][j+1]*xv[j+1]; }
            part[half][i] = s0 + s1;
        }
        __syncthreads();
        if (tid < 100) xv[tid] = part[0][tid] + part[1][tid] + 1.f/Ssz;
        __syncthreads();
    }
    if (tid < 100) out[(size_t)b*Ssz + tid] = (1.f - LAMBf)*xv[tid];
}

// ---------------- launch: two-stream fork (proven) + fp16 GEMMs --------------------
extern "C" void kernel_launch(void* const* d_in, const int* in_sizes, int n_in,
                              void* d_out, int out_size) {
    const float* X    = (const float*)d_in[0];
    const int*   mask = (const int*)  d_in[1];
    const float* Wc   = (const float*)d_in[2];
    const float* Wsim = (const float*)d_in[3];
    const float* Wrel = (const float*)d_in[4];
    const float* bm   = (const float*)d_in[5];
    float* out = (float*)d_out;

    float *drep, *wd;
    __half *wsimTh, *Xh, *T1h;
    cudaGetSymbolAddress((void**)&drep,   g_drep);
    cudaGetSymbolAddress((void**)&wsimTh, g_wsimTh);
    cudaGetSymbolAddress((void**)&Xh,     g_Xh);
    cudaGetSymbolAddress((void**)&wd,     g_wd);
    cudaGetSymbolAddress((void**)&T1h,    g_T1h);

    cudaStream_t s2 = 0;
    cudaEvent_t  e1 = 0, e2 = 0;
    bool fork = (cudaStreamCreateWithFlags(&s2, cudaStreamNonBlocking) == cudaSuccess);
    if (fork) fork = (cudaEventCreateWithFlags(&e1, cudaEventDisableTiming) == cudaSuccess);
    if (fork) fork = (cudaEventCreateWithFlags(&e2, cudaEventDisableTiming) == cudaSuccess);
    if (fork) fork = (cudaEventRecord(e1, 0) == cudaSuccess) &&
                     (cudaStreamWaitEvent(s2, e1, 0) == cudaSuccess);
    cudaStream_t sb = fork ? s2 : (cudaStream_t)0;

    // Branch A: convert X + W_sim^T to fp16, then fp16 big GEMM T1h = Xh @ Wsim
    k_convX<<<2048, 256>>>((const float4*)X, (__half2*)Xh, BS*Hsz/4);
    k_transpose_h<<<dim3(Hsz/32, Hsz/32), dim3(32, 8)>>>(Wsim, wsimTh);
    k_gemm_h<<<dim3(Hsz/128, BS/128), 256>>>(Xh, wsimTh, T1h, BS, Hsz, Hsz);

    // Branch B: mean -> wd GEMM (tf32) -> cont/rel (fp32)
    k_mean<<<Bsz, 256, 0, sb>>>(X);
    k_gemm_nt32<<<dim3(Hsz/128, Bsz/32), 256, 0, sb>>>(drep, Wrel, wd, Bsz, Hsz, Hsz);
    k_cont_rel<<<BS/8, 256, 0, sb>>>(X, Wc);

    if (fork) {
        cudaEventRecord(e2, s2);
        cudaStreamWaitEvent(0, e2, 0);
    }

    // Join: fp16 sim + sigmoid -> q, then batched solve
    k_sim_q_h<<<Bsz, 256>>>(mask, bm);
    k_solve<<<Bsz, 256>>>(out);

    cudaStreamCaptureStatus cs = cudaStreamCaptureStatusNone;
    cudaStreamIsCapturing(0, &cs);
    if (cs == cudaStreamCaptureStatusNone) {
        if (e1) cudaEventDestroy(e1);
        if (e2) cudaEventDestroy(e2);
        if (s2) cudaStreamDestroy(s2);
    }
}